// round 9
// baseline (speedup 1.0000x reference)
#include <cuda_runtime.h>
#include <cuda_fp16.h>
#include <cstdint>

typedef unsigned long long ull;

// Problem constants
#define BB 4
#define NN 2048
#define II 32
#define HH 64
#define OO 32
#define EE 2
#define HD 2
#define EH 4              // E*HD
#define CC 16             // EH*B combos
#define D1 256            // H*HD*E
#define BNN 16777216      // B*N*N
#define SLAB (NN*NN/2)    // half2 per (e,b) slab

// ---------------- scratch (device globals; no allocation) ----------------
__device__ __half2 g_edgeH2[BNN];            // [e][b][i][k] fp16, 67MB
__device__ float g_state0[BB * NN * HH];
__device__ float g_state1[BB * NN * D1];
__device__ float g_Wh [CC * NN * HH];
__device__ __half2 g_WhnT[CC * 64 * 1024];   // [c][d][k/2]  fp16 normalized transposed
__device__ float g_a1[CC * NN];
__device__ float g_a2[CC * NN];
__device__ float g_s [CC * NN];
__device__ float g_spart[8 * CC * NN];
__device__ float g_msg1[CC * NN * HH];
__device__ float g_partial[BB * 16 * HH];

// ---------------- f32x2 packed helpers (Blackwell FFMA2) ----------------
__device__ __forceinline__ ull pk2(float x) {
    ull r;
    asm("mov.b64 %0, {%1, %1};" : "=l"(r) : "f"(x));
    return r;
}
__device__ __forceinline__ void fma2(ull& d, ull a, ull b) {
    asm("fma.rn.f32x2 %0, %1, %2, %0;" : "+l"(d) : "l"(a), "l"(b));
}
__device__ __forceinline__ void upk2(ull v, float& lo, float& hi) {
    asm("mov.b64 {%0, %1}, %2;" : "=f"(lo), "=f"(hi) : "l"(v));
}

// ---------------- HMMA helper: m16n8k16 fp16 -> fp32 ----------------
__device__ __forceinline__ void mma16816(float* d,
                                         uint32_t a0, uint32_t a1,
                                         uint32_t a2, uint32_t a3,
                                         uint32_t b0, uint32_t b1) {
    asm volatile(
        "mma.sync.aligned.m16n8k16.row.col.f32.f16.f16.f32 "
        "{%0,%1,%2,%3}, {%4,%5,%6,%7}, {%8,%9}, {%0,%1,%2,%3};"
        : "+f"(d[0]), "+f"(d[1]), "+f"(d[2]), "+f"(d[3])
        : "r"(a0), "r"(a1), "r"(a2), "r"(a3), "r"(b0), "r"(b1));
}

// exp of a k-pair packed to half2 (bit pattern as u32 for the MMA frag)
__device__ __forceinline__ uint32_t expp(float a1v, float2 a2v, __half2 ev) {
    float2 e = __half22float2(ev);
    float l0 = a1v + a2v.x; l0 = l0 > 0.f ? l0 : 0.2f * l0;
    float l1 = a1v + a2v.y; l1 = l1 > 0.f ? l1 : 0.2f * l1;
    __half2 h = __floats2half2_rn(__expf(l0 + e.x), __expf(l1 + e.y));
    return *reinterpret_cast<uint32_t*>(&h);
}
__device__ __forceinline__ uint32_t h2u(__half2 h) {
    return *reinterpret_cast<uint32_t*>(&h);
}

// ---------------- kernels ----------------

// split interleaved fp32 edges (B,N,N,E) -> two contiguous fp16 slabs
__global__ void k_split_edges(const float* __restrict__ edges) {
    size_t t = (size_t)blockIdx.x * blockDim.x + threadIdx.x;  // over BNN/2 float4s
    float4 v = ((const float4*)edges)[t];
    g_edgeH2[t]           = __floats2half2_rn(v.x, v.z);   // e=0
    g_edgeH2[BNN / 2 + t] = __floats2half2_rn(v.y, v.w);   // e=1
}

// state0 = nodes @ W_emb + b_emb
__global__ void k_embed(const float* __restrict__ nodes,
                        const float* __restrict__ Wemb,
                        const float* __restrict__ bemb) {
    __shared__ float sW[II * HH];
    int tid = threadIdx.x;
    for (int i = tid; i < II * HH; i += 256) sW[i] = Wemb[i];
    __syncthreads();
    int row = blockIdx.x * 4 + (tid >> 6);
    int h = tid & 63;
    const float* nr = nodes + (size_t)row * II;
    float acc = bemb[h];
#pragma unroll
    for (int d = 0; d < II; d++) acc += __ldg(&nr[d]) * sW[d * HH + h];
    g_state0[(size_t)row * HH + h] = acc;
}

// Wh[eh,b,n,:] = state @ Wf[eh]   64x64 tile, FFMA2 micro-kernel
template <int DIN>
__global__ void __launch_bounds__(128) k_wh(const float* __restrict__ Wf) {
    __shared__ float sS[64][66];
    __shared__ __align__(16) float sW[64][68];
    const float* src = (DIN == 64) ? g_state0 : g_state1;
    int tid = threadIdx.x;
    int n0 = blockIdx.x * 64;
    int b = blockIdx.y;
    int eh = blockIdx.z;
    const float* Wfe = Wf + (size_t)eh * DIN * 64;
    const float* S = src + ((size_t)b * NN + n0) * DIN;
    int ti = tid >> 3, td = tid & 7;
    int ry = tid >> 1, xs = (tid & 1) * 32;
    ull acc[16];
#pragma unroll
    for (int r = 0; r < 16; r++) acc[r] = 0ULL;

    for (int d0 = 0; d0 < DIN; d0 += 64) {
        __syncthreads();
#pragma unroll
        for (int j = 0; j < 8; j++) {
            float4 v = *(const float4*)&S[(size_t)ry * DIN + d0 + xs + 4 * j];
            sS[ry][xs + 4 * j + 0] = v.x;
            sS[ry][xs + 4 * j + 1] = v.y;
            sS[ry][xs + 4 * j + 2] = v.z;
            sS[ry][xs + 4 * j + 3] = v.w;
        }
#pragma unroll
        for (int j = 0; j < 8; j++)
            *(float4*)&sW[ry][xs + 4 * j] =
                *(const float4*)&Wfe[(size_t)(d0 + ry) * 64 + xs + 4 * j];
        __syncthreads();
#pragma unroll 8
        for (int d = 0; d < 64; d++) {
            const ull* wp = (const ull*)&sW[d][8 * td];
            ull w0 = wp[0], w1 = wp[1], w2v = wp[2], w3 = wp[3];
#pragma unroll
            for (int r = 0; r < 4; r++) {
                ull s = pk2(sS[4 * ti + r][d]);
                fma2(acc[4 * r + 0], s, w0);
                fma2(acc[4 * r + 1], s, w1);
                fma2(acc[4 * r + 2], s, w2v);
                fma2(acc[4 * r + 3], s, w3);
            }
        }
    }
    size_t base = (size_t)(eh * BB + b) * NN + n0;
#pragma unroll
    for (int r = 0; r < 4; r++) {
        float o[8];
        upk2(acc[4 * r + 0], o[0], o[1]);
        upk2(acc[4 * r + 1], o[2], o[3]);
        upk2(acc[4 * r + 2], o[4], o[5]);
        upk2(acc[4 * r + 3], o[6], o[7]);
        float* dst = &g_Wh[(base + 4 * ti + r) * 64 + 8 * td];
        *(float4*)dst = make_float4(o[0], o[1], o[2], o[3]);
        *(float4*)(dst + 4) = make_float4(o[4], o[5], o[6], o[7]);
    }
}

// a1 = Wh . w1 + b1 ; a2 = Wh . w2 + b2
__global__ void k_a12(const float* __restrict__ w1, const float* __restrict__ b1,
                      const float* __restrict__ w2, const float* __restrict__ b2) {
    int warp = (blockIdx.x * blockDim.x + threadIdx.x) >> 5;
    int lane = threadIdx.x & 31;
    int c = warp >> 11;
    int eh = c >> 2;
    const float* wh = g_Wh + (size_t)warp * 64;
    float x0 = wh[lane], x1 = wh[lane + 32];
    float d1 = x0 * w1[eh * 64 + lane] + x1 * w1[eh * 64 + lane + 32];
    float d2 = x0 * w2[eh * 64 + lane] + x1 * w2[eh * 64 + lane + 32];
#pragma unroll
    for (int o = 16; o; o >>= 1) {
        d1 += __shfl_down_sync(0xffffffffu, d1, o);
        d2 += __shfl_down_sync(0xffffffffu, d2, o);
    }
    if (lane == 0) {
        g_a1[warp] = d1 + b1[eh];
        g_a2[warp] = d2 + b2[eh];
    }
}

// partial s[k] over a 256-row i-chunk; grid (ktile=4, ichunk=8, c=16)
__global__ void __launch_bounds__(256) k_stats() {
    __shared__ float sA1[256];
    int c = blockIdx.z;
    int e = c >> 3, b = c & 3;
    int tid = threadIdx.x;
    int kbase = blockIdx.x * 512;
    int i0 = blockIdx.y * 256;
    sA1[tid] = g_a1[c * NN + i0 + tid];
    __syncthreads();
    int k = kbase + 2 * tid;
    float a20 = g_a2[c * NN + k], a21 = g_a2[c * NN + k + 1];
    const __half2* eg = g_edgeH2 + (size_t)(e * BB + b) * SLAB +
                        (size_t)i0 * (NN / 2) + (kbase >> 1) + tid;
    float s0 = 0.f, s1 = 0.f;
#pragma unroll 8
    for (int i = 0; i < 256; i++) {
        float2 ev = __half22float2(eg[(size_t)i * (NN / 2)]);
        float v = sA1[i];
        float l0 = v + a20; l0 = l0 > 0.f ? l0 : 0.2f * l0;
        float l1 = v + a21; l1 = l1 > 0.f ? l1 : 0.2f * l1;
        s0 += __expf(l0 + ev.x);
        s1 += __expf(l1 + ev.y);
    }
    float2* sp = (float2*)(g_spart + ((size_t)blockIdx.y * CC + c) * NN);
    sp[(kbase >> 1) + tid] = make_float2(s0, s1);
}

// reduce 8 partials -> g_s
__global__ void k_sred() {
    int idx = blockIdx.x * 256 + threadIdx.x;
    float s = 0.f;
#pragma unroll
    for (int ic = 0; ic < 8; ic++) s += g_spart[(size_t)ic * CC * NN + idx];
    g_s[idx] = s;
}

// WhnT[c][d][k] = (Wh[c][k][d] / s[c][k]) as fp16, transposed
__global__ void __launch_bounds__(256) k_whnT() {
    __shared__ float tl[64][65];
    int c = blockIdx.y;
    int k0 = blockIdx.x * 64;
    int tid = threadIdx.x;
    int ky = tid >> 6, d = tid & 63;
#pragma unroll
    for (int p = 0; p < 16; p++)
        tl[4 * p + ky][d] = g_Wh[((size_t)c * NN + k0 + 4 * p + ky) * 64 + d];
    __syncthreads();
    int lam = tid & 31, dw = tid >> 5;
    float2 s2 = *(const float2*)&g_s[c * NN + k0 + 2 * lam];
    float rx = __fdividef(1.f, s2.x), ry = __fdividef(1.f, s2.y);
#pragma unroll
    for (int q = 0; q < 8; q++) {
        int dd = dw * 8 + q;
        g_WhnT[(size_t)(c * 64 + dd) * 1024 + (k0 >> 1) + lam] =
            __floats2half2_rn(tl[2 * lam][dd] * rx, tl[2 * lam + 1][dd] * ry);
    }
}

// msg via HMMA m16n8k16: D[128 i, 64 d] = sum_k exp(...)[i,k] * WhnT[d,k]
// No shared memory: A fragments computed in registers, B loaded straight
// from global (fragment layouts match the half2 storage exactly).
template <int LAYER>
__global__ void __launch_bounds__(256) k_msg_mma(const float* __restrict__ bias) {
    int tid = threadIdx.x;
    int w = tid >> 5, lane = tid & 31;
    int grp = lane >> 2, qd = lane & 3;
    int c = blockIdx.y;
    int eh = c >> 2, b = c & 3;
    int e = eh >> 1, h = eh & 1;
    int i0 = blockIdx.x * 128;
    int iw = i0 + 16 * w;

    const __half2* eslab = g_edgeH2 + (size_t)(e * BB + b) * SLAB;
    const __half2* wT = g_WhnT + (size_t)c * 64 * 1024;
    const float* a2p = g_a2 + c * NN;

    float a1lo = g_a1[c * NN + iw + grp];
    float a1hi = g_a1[c * NN + iw + grp + 8];

    const __half2* erow_lo = eslab + (size_t)(iw + grp) * (NN / 2);
    const __half2* erow_hi = erow_lo + (size_t)8 * (NN / 2);

    float acc[8][4];
#pragma unroll
    for (int nt = 0; nt < 8; nt++)
#pragma unroll
        for (int j = 0; j < 4; j++) acc[nt][j] = 0.f;

    // edge double-buffer
    __half2 e0 = erow_lo[qd], e1 = erow_lo[qd + 4];
    __half2 e2 = erow_hi[qd], e3 = erow_hi[qd + 4];

#pragma unroll 2
    for (int t = 0; t < 128; t++) {
        int kh = 8 * t;
        __half2 c0 = e0, c1 = e1, c2 = e2, c3 = e3;
        if (t < 127) {
            e0 = erow_lo[kh + 8 + qd]; e1 = erow_lo[kh + 8 + qd + 4];
            e2 = erow_hi[kh + 8 + qd]; e3 = erow_hi[kh + 8 + qd + 4];
        }
        float2 a2lo = *(const float2*)&a2p[16 * t + 2 * qd];
        float2 a2hi = *(const float2*)&a2p[16 * t + 2 * qd + 8];

        uint32_t A0 = expp(a1lo, a2lo, c0);   // rows 0-7,  k 0-7
        uint32_t A1 = expp(a1hi, a2lo, c2);   // rows 8-15, k 0-7
        uint32_t A2 = expp(a1lo, a2hi, c1);   // rows 0-7,  k 8-15
        uint32_t A3 = expp(a1hi, a2hi, c3);   // rows 8-15, k 8-15

#pragma unroll
        for (int nt = 0; nt < 8; nt++) {
            const __half2* bp = wT + (size_t)(8 * nt + grp) * 1024 + kh + qd;
            uint32_t B0 = h2u(bp[0]);
            uint32_t B1 = h2u(bp[4]);
            mma16816(acc[nt], A0, A1, A2, A3, B0, B1);
        }
    }

    // store: c0,c1 -> (row grp, cols 2qd,2qd+1); c2,c3 -> row grp+8
    int gi_lo = iw + grp, gi_hi = iw + grp + 8;
#pragma unroll
    for (int nt = 0; nt < 8; nt++) {
        int col = 8 * nt + 2 * qd;
        float bx = bias[h * 64 + col], by = bias[h * 64 + col + 1];
        float2 vlo = make_float2(acc[nt][0] + bx, acc[nt][1] + by);
        float2 vhi = make_float2(acc[nt][2] + bx, acc[nt][3] + by);
        if (LAYER == 0) {
            *(float2*)&g_state1[((size_t)b * NN + gi_lo) * D1 + eh * 64 + col] = vlo;
            *(float2*)&g_state1[((size_t)b * NN + gi_hi) * D1 + eh * 64 + col] = vhi;
        } else {
            *(float2*)&g_msg1[((size_t)c * NN + gi_lo) * 64 + col] = vlo;
            *(float2*)&g_msg1[((size_t)c * NN + gi_hi) * 64 + col] = vhi;
        }
    }
}

// partial[b,chunk,h] = sum over eh and 128 n-rows of elu(msg1)
__global__ void k_reduce1() {
    int b = blockIdx.y, ch = blockIdx.x;
    int n0 = ch * 128;
    int h = threadIdx.x & 63, sub = threadIdx.x >> 6;
    float s = 0.f;
#pragma unroll
    for (int eh = 0; eh < EH; eh++) {
        const float* m = g_msg1 + ((size_t)(eh * BB + b) * NN + n0) * 64;
        for (int n = sub; n < 128; n += 4) {
            float x = m[(size_t)n * 64 + h];
            s += x > 0.f ? x : expm1f(x);
        }
    }
    __shared__ float red[256];
    red[threadIdx.x] = s;
    __syncthreads();
    if (threadIdx.x < 64)
        g_partial[(b * 16 + ch) * 64 + threadIdx.x] =
            red[threadIdx.x] + red[64 + threadIdx.x] +
            red[128 + threadIdx.x] + red[192 + threadIdx.x];
}

__global__ void k_out(const float* __restrict__ Wout,
                      const float* __restrict__ bout,
                      float* __restrict__ out) {
    __shared__ float v[BB * 64];
    int t = threadIdx.x;
    {
        int b = t >> 6, h = t & 63;
        float s = 0.f;
#pragma unroll
        for (int p = 0; p < 16; p++) s += g_partial[(b * 16 + p) * 64 + h];
        v[t] = s;
    }
    __syncthreads();
    if (t < 128) {
        int b = t >> 5, o = t & 31;
        float s = 0.f;
#pragma unroll
        for (int hh = 0; hh < 64; hh++) s += v[b * 64 + hh] * Wout[hh * OO + o];
        out[b * OO + o] = s * (1.f / 8192.f) + bout[o];
    }
}

// ---------------- launcher ----------------
extern "C" void kernel_launch(void* const* d_in, const int* in_sizes, int n_in,
                              void* d_out, int out_size) {
    const float* nodes = (const float*)d_in[0];
    const float* edges = (const float*)d_in[1];
    const float* W_emb = (const float*)d_in[2];
    const float* b_emb = (const float*)d_in[3];
    const float* Wf0   = (const float*)d_in[4];
    const float* w1_0  = (const float*)d_in[5];
    const float* b1_0  = (const float*)d_in[6];
    const float* w2_0  = (const float*)d_in[7];
    const float* b2_0  = (const float*)d_in[8];
    const float* bias0 = (const float*)d_in[9];
    const float* Wf1   = (const float*)d_in[10];
    const float* w1_1  = (const float*)d_in[11];
    const float* b1_1  = (const float*)d_in[12];
    const float* w2_1  = (const float*)d_in[13];
    const float* b2_1  = (const float*)d_in[14];
    const float* bias1 = (const float*)d_in[15];
    const float* W_out = (const float*)d_in[16];
    const float* b_out = (const float*)d_in[17];
    float* out = (float*)d_out;

    k_split_edges<<<BNN / 2 / 256, 256>>>(edges);
    k_embed<<<(BB * NN) / 4, 256>>>(nodes, W_emb, b_emb);

    // ---- layer 0 (DIN = 64) ----
    k_wh<64><<<dim3(NN / 64, BB, EH), 128>>>(Wf0);
    k_a12<<<(CC * NN * 32) / 256, 256>>>(w1_0, b1_0, w2_0, b2_0);
    k_stats<<<dim3(4, 8, CC), 256>>>();
    k_sred<<<CC * NN / 256, 256>>>();
    k_whnT<<<dim3(NN / 64, CC), 256>>>();
    k_msg_mma<0><<<dim3(NN / 128, CC), 256>>>(bias0);

    // ---- layer 1 (DIN = 256) ----
    k_wh<256><<<dim3(NN / 64, BB, EH), 128>>>(Wf1);
    k_a12<<<(CC * NN * 32) / 256, 256>>>(w1_1, b1_1, w2_1, b2_1);
    k_stats<<<dim3(4, 8, CC), 256>>>();
    k_sred<<<CC * NN / 256, 256>>>();
    k_whnT<<<dim3(NN / 64, CC), 256>>>();
    k_msg_mma<1><<<dim3(NN / 128, CC), 256>>>(bias1);

    // ---- final reduction + output head ----
    k_reduce1<<<dim3(16, BB), 256>>>();
    k_out<<<1, 256>>>(W_out, b_out, out);
}

// round 10
// speedup vs baseline: 1.0036x; 1.0036x over previous
#include <cuda_runtime.h>
#include <cuda_fp16.h>
#include <cstdint>

typedef unsigned long long ull;

// Problem constants
#define BB 4
#define NN 2048
#define II 32
#define HH 64
#define OO 32
#define EE 2
#define HD 2
#define EH 4              // E*HD
#define CC 16             // EH*B combos
#define D1 256            // H*HD*E
#define BNN 16777216      // B*N*N
#define SLAB (NN*NN/2)    // half2 per (e,b) slab

// ---------------- scratch (device globals; no allocation) ----------------
__device__ __half2 g_edgeH2[BNN];            // [e][b][i][k] fp16, 67MB
__device__ float g_state0[BB * NN * HH];
__device__ float g_state1[BB * NN * D1];
__device__ float g_Wh [CC * NN * HH];
__device__ __half2 g_WhnT[CC * 64 * 1024];   // [c][d][k/2]  fp16 normalized transposed
__device__ float g_a1[CC * NN];
__device__ float g_a2[CC * NN];
__device__ float g_s [CC * NN];
__device__ float g_spart[8 * CC * NN];
__device__ float g_msg1[CC * NN * HH];
__device__ float g_partial[BB * 16 * HH];

// ---------------- f32x2 packed helpers (Blackwell FFMA2) ----------------
__device__ __forceinline__ ull pk2(float x) {
    ull r;
    asm("mov.b64 %0, {%1, %1};" : "=l"(r) : "f"(x));
    return r;
}
__device__ __forceinline__ void fma2(ull& d, ull a, ull b) {
    asm("fma.rn.f32x2 %0, %1, %2, %0;" : "+l"(d) : "l"(a), "l"(b));
}
__device__ __forceinline__ void upk2(ull v, float& lo, float& hi) {
    asm("mov.b64 {%0, %1}, %2;" : "=f"(lo), "=f"(hi) : "l"(v));
}

// ---------------- HMMA helper: m16n8k16 fp16 -> fp32 ----------------
__device__ __forceinline__ void mma16816(float* d,
                                         uint32_t a0, uint32_t a1,
                                         uint32_t a2, uint32_t a3,
                                         uint32_t b0, uint32_t b1) {
    asm volatile(
        "mma.sync.aligned.m16n8k16.row.col.f32.f16.f16.f32 "
        "{%0,%1,%2,%3}, {%4,%5,%6,%7}, {%8,%9}, {%0,%1,%2,%3};"
        : "+f"(d[0]), "+f"(d[1]), "+f"(d[2]), "+f"(d[3])
        : "r"(a0), "r"(a1), "r"(a2), "r"(a3), "r"(b0), "r"(b1));
}

// exp of a k-pair packed to half2 (bit pattern as u32 for the MMA frag)
__device__ __forceinline__ uint32_t expp(float a1v, float2 a2v, __half2 ev) {
    float2 e = __half22float2(ev);
    float l0 = a1v + a2v.x; l0 = l0 > 0.f ? l0 : 0.2f * l0;
    float l1 = a1v + a2v.y; l1 = l1 > 0.f ? l1 : 0.2f * l1;
    __half2 h = __floats2half2_rn(__expf(l0 + e.x), __expf(l1 + e.y));
    return *reinterpret_cast<uint32_t*>(&h);
}
__device__ __forceinline__ uint32_t h2u(__half2 h) {
    return *reinterpret_cast<uint32_t*>(&h);
}

// ---------------- kernels ----------------

// split interleaved fp32 edges (B,N,N,E) -> two contiguous fp16 slabs
__global__ void k_split_edges(const float* __restrict__ edges) {
    size_t t = (size_t)blockIdx.x * blockDim.x + threadIdx.x;  // over BNN/2 float4s
    float4 v = ((const float4*)edges)[t];
    g_edgeH2[t]           = __floats2half2_rn(v.x, v.z);   // e=0
    g_edgeH2[BNN / 2 + t] = __floats2half2_rn(v.y, v.w);   // e=1
}

// state0 = nodes @ W_emb + b_emb
__global__ void k_embed(const float* __restrict__ nodes,
                        const float* __restrict__ Wemb,
                        const float* __restrict__ bemb) {
    __shared__ float sW[II * HH];
    int tid = threadIdx.x;
    for (int i = tid; i < II * HH; i += 256) sW[i] = Wemb[i];
    __syncthreads();
    int row = blockIdx.x * 4 + (tid >> 6);
    int h = tid & 63;
    const float* nr = nodes + (size_t)row * II;
    float acc = bemb[h];
#pragma unroll
    for (int d = 0; d < II; d++) acc += __ldg(&nr[d]) * sW[d * HH + h];
    g_state0[(size_t)row * HH + h] = acc;
}

// Wh[eh,b,n,:] = state @ Wf[eh]   64x64 tile, FFMA2 micro-kernel
template <int DIN>
__global__ void __launch_bounds__(128) k_wh(const float* __restrict__ Wf) {
    __shared__ float sS[64][66];
    __shared__ __align__(16) float sW[64][68];
    const float* src = (DIN == 64) ? g_state0 : g_state1;
    int tid = threadIdx.x;
    int n0 = blockIdx.x * 64;
    int b = blockIdx.y;
    int eh = blockIdx.z;
    const float* Wfe = Wf + (size_t)eh * DIN * 64;
    const float* S = src + ((size_t)b * NN + n0) * DIN;
    int ti = tid >> 3, td = tid & 7;
    int ry = tid >> 1, xs = (tid & 1) * 32;
    ull acc[16];
#pragma unroll
    for (int r = 0; r < 16; r++) acc[r] = 0ULL;

    for (int d0 = 0; d0 < DIN; d0 += 64) {
        __syncthreads();
#pragma unroll
        for (int j = 0; j < 8; j++) {
            float4 v = *(const float4*)&S[(size_t)ry * DIN + d0 + xs + 4 * j];
            sS[ry][xs + 4 * j + 0] = v.x;
            sS[ry][xs + 4 * j + 1] = v.y;
            sS[ry][xs + 4 * j + 2] = v.z;
            sS[ry][xs + 4 * j + 3] = v.w;
        }
#pragma unroll
        for (int j = 0; j < 8; j++)
            *(float4*)&sW[ry][xs + 4 * j] =
                *(const float4*)&Wfe[(size_t)(d0 + ry) * 64 + xs + 4 * j];
        __syncthreads();
#pragma unroll 8
        for (int d = 0; d < 64; d++) {
            const ull* wp = (const ull*)&sW[d][8 * td];
            ull w0 = wp[0], w1 = wp[1], w2v = wp[2], w3 = wp[3];
#pragma unroll
            for (int r = 0; r < 4; r++) {
                ull s = pk2(sS[4 * ti + r][d]);
                fma2(acc[4 * r + 0], s, w0);
                fma2(acc[4 * r + 1], s, w1);
                fma2(acc[4 * r + 2], s, w2v);
                fma2(acc[4 * r + 3], s, w3);
            }
        }
    }
    size_t base = (size_t)(eh * BB + b) * NN + n0;
#pragma unroll
    for (int r = 0; r < 4; r++) {
        float o[8];
        upk2(acc[4 * r + 0], o[0], o[1]);
        upk2(acc[4 * r + 1], o[2], o[3]);
        upk2(acc[4 * r + 2], o[4], o[5]);
        upk2(acc[4 * r + 3], o[6], o[7]);
        float* dst = &g_Wh[(base + 4 * ti + r) * 64 + 8 * td];
        *(float4*)dst = make_float4(o[0], o[1], o[2], o[3]);
        *(float4*)(dst + 4) = make_float4(o[4], o[5], o[6], o[7]);
    }
}

// a1 = Wh . w1 + b1 ; a2 = Wh . w2 + b2
__global__ void k_a12(const float* __restrict__ w1, const float* __restrict__ b1,
                      const float* __restrict__ w2, const float* __restrict__ b2) {
    int warp = (blockIdx.x * blockDim.x + threadIdx.x) >> 5;
    int lane = threadIdx.x & 31;
    int c = warp >> 11;
    int eh = c >> 2;
    const float* wh = g_Wh + (size_t)warp * 64;
    float x0 = wh[lane], x1 = wh[lane + 32];
    float d1 = x0 * w1[eh * 64 + lane] + x1 * w1[eh * 64 + lane + 32];
    float d2 = x0 * w2[eh * 64 + lane] + x1 * w2[eh * 64 + lane + 32];
#pragma unroll
    for (int o = 16; o; o >>= 1) {
        d1 += __shfl_down_sync(0xffffffffu, d1, o);
        d2 += __shfl_down_sync(0xffffffffu, d2, o);
    }
    if (lane == 0) {
        g_a1[warp] = d1 + b1[eh];
        g_a2[warp] = d2 + b2[eh];
    }
}

// partial s[k] over a 256-row i-chunk; grid (ktile=4, ichunk=8, c=16)
__global__ void __launch_bounds__(256) k_stats() {
    __shared__ float sA1[256];
    int c = blockIdx.z;
    int e = c >> 3, b = c & 3;
    int tid = threadIdx.x;
    int kbase = blockIdx.x * 512;
    int i0 = blockIdx.y * 256;
    sA1[tid] = g_a1[c * NN + i0 + tid];
    __syncthreads();
    int k = kbase + 2 * tid;
    float a20 = g_a2[c * NN + k], a21 = g_a2[c * NN + k + 1];
    const __half2* eg = g_edgeH2 + (size_t)(e * BB + b) * SLAB +
                        (size_t)i0 * (NN / 2) + (kbase >> 1) + tid;
    float s0 = 0.f, s1 = 0.f;
#pragma unroll 8
    for (int i = 0; i < 256; i++) {
        float2 ev = __half22float2(eg[(size_t)i * (NN / 2)]);
        float v = sA1[i];
        float l0 = v + a20; l0 = l0 > 0.f ? l0 : 0.2f * l0;
        float l1 = v + a21; l1 = l1 > 0.f ? l1 : 0.2f * l1;
        s0 += __expf(l0 + ev.x);
        s1 += __expf(l1 + ev.y);
    }
    float2* sp = (float2*)(g_spart + ((size_t)blockIdx.y * CC + c) * NN);
    sp[(kbase >> 1) + tid] = make_float2(s0, s1);
}

// reduce 8 partials -> g_s
__global__ void k_sred() {
    int idx = blockIdx.x * 256 + threadIdx.x;
    float s = 0.f;
#pragma unroll
    for (int ic = 0; ic < 8; ic++) s += g_spart[(size_t)ic * CC * NN + idx];
    g_s[idx] = s;
}

// WhnT[c][d][k] = (Wh[c][k][d] / s[c][k]) as fp16, transposed
__global__ void __launch_bounds__(256) k_whnT() {
    __shared__ float tl[64][65];
    int c = blockIdx.y;
    int k0 = blockIdx.x * 64;
    int tid = threadIdx.x;
    int ky = tid >> 6, d = tid & 63;
#pragma unroll
    for (int p = 0; p < 16; p++)
        tl[4 * p + ky][d] = g_Wh[((size_t)c * NN + k0 + 4 * p + ky) * 64 + d];
    __syncthreads();
    int lam = tid & 31, dw = tid >> 5;
    float2 s2 = *(const float2*)&g_s[c * NN + k0 + 2 * lam];
    float rx = __fdividef(1.f, s2.x), ry = __fdividef(1.f, s2.y);
#pragma unroll
    for (int q = 0; q < 8; q++) {
        int dd = dw * 8 + q;
        g_WhnT[(size_t)(c * 64 + dd) * 1024 + (k0 >> 1) + lam] =
            __floats2half2_rn(tl[2 * lam][dd] * rx, tl[2 * lam + 1][dd] * ry);
    }
}

// msg via HMMA m16n8k16: D[128 i, 64 d] = sum_k exp(...)[i,k] * WhnT[d,k]
// No shared memory: A fragments computed in registers, B loaded straight
// from global (fragment layouts match the half2 storage exactly).
template <int LAYER>
__global__ void __launch_bounds__(256) k_msg_mma(const float* __restrict__ bias) {
    int tid = threadIdx.x;
    int w = tid >> 5, lane = tid & 31;
    int grp = lane >> 2, qd = lane & 3;
    int c = blockIdx.y;
    int eh = c >> 2, b = c & 3;
    int e = eh >> 1, h = eh & 1;
    int i0 = blockIdx.x * 128;
    int iw = i0 + 16 * w;

    const __half2* eslab = g_edgeH2 + (size_t)(e * BB + b) * SLAB;
    const __half2* wT = g_WhnT + (size_t)c * 64 * 1024;
    const float* a2p = g_a2 + c * NN;

    float a1lo = g_a1[c * NN + iw + grp];
    float a1hi = g_a1[c * NN + iw + grp + 8];

    const __half2* erow_lo = eslab + (size_t)(iw + grp) * (NN / 2);
    const __half2* erow_hi = erow_lo + (size_t)8 * (NN / 2);

    float acc[8][4];
#pragma unroll
    for (int nt = 0; nt < 8; nt++)
#pragma unroll
        for (int j = 0; j < 4; j++) acc[nt][j] = 0.f;

    // edge double-buffer
    __half2 e0 = erow_lo[qd], e1 = erow_lo[qd + 4];
    __half2 e2 = erow_hi[qd], e3 = erow_hi[qd + 4];

#pragma unroll 2
    for (int t = 0; t < 128; t++) {
        int kh = 8 * t;
        __half2 c0 = e0, c1 = e1, c2 = e2, c3 = e3;
        if (t < 127) {
            e0 = erow_lo[kh + 8 + qd]; e1 = erow_lo[kh + 8 + qd + 4];
            e2 = erow_hi[kh + 8 + qd]; e3 = erow_hi[kh + 8 + qd + 4];
        }
        float2 a2lo = *(const float2*)&a2p[16 * t + 2 * qd];
        float2 a2hi = *(const float2*)&a2p[16 * t + 2 * qd + 8];

        uint32_t A0 = expp(a1lo, a2lo, c0);   // rows 0-7,  k 0-7
        uint32_t A1 = expp(a1hi, a2lo, c2);   // rows 8-15, k 0-7
        uint32_t A2 = expp(a1lo, a2hi, c1);   // rows 0-7,  k 8-15
        uint32_t A3 = expp(a1hi, a2hi, c3);   // rows 8-15, k 8-15

#pragma unroll
        for (int nt = 0; nt < 8; nt++) {
            const __half2* bp = wT + (size_t)(8 * nt + grp) * 1024 + kh + qd;
            uint32_t B0 = h2u(bp[0]);
            uint32_t B1 = h2u(bp[4]);
            mma16816(acc[nt], A0, A1, A2, A3, B0, B1);
        }
    }

    // store: c0,c1 -> (row grp, cols 2qd,2qd+1); c2,c3 -> row grp+8
    int gi_lo = iw + grp, gi_hi = iw + grp + 8;
#pragma unroll
    for (int nt = 0; nt < 8; nt++) {
        int col = 8 * nt + 2 * qd;
        float bx = bias[h * 64 + col], by = bias[h * 64 + col + 1];
        float2 vlo = make_float2(acc[nt][0] + bx, acc[nt][1] + by);
        float2 vhi = make_float2(acc[nt][2] + bx, acc[nt][3] + by);
        if (LAYER == 0) {
            *(float2*)&g_state1[((size_t)b * NN + gi_lo) * D1 + eh * 64 + col] = vlo;
            *(float2*)&g_state1[((size_t)b * NN + gi_hi) * D1 + eh * 64 + col] = vhi;
        } else {
            *(float2*)&g_msg1[((size_t)c * NN + gi_lo) * 64 + col] = vlo;
            *(float2*)&g_msg1[((size_t)c * NN + gi_hi) * 64 + col] = vhi;
        }
    }
}

// partial[b,chunk,h] = sum over eh and 128 n-rows of elu(msg1)
__global__ void k_reduce1() {
    int b = blockIdx.y, ch = blockIdx.x;
    int n0 = ch * 128;
    int h = threadIdx.x & 63, sub = threadIdx.x >> 6;
    float s = 0.f;
#pragma unroll
    for (int eh = 0; eh < EH; eh++) {
        const float* m = g_msg1 + ((size_t)(eh * BB + b) * NN + n0) * 64;
        for (int n = sub; n < 128; n += 4) {
            float x = m[(size_t)n * 64 + h];
            s += x > 0.f ? x : expm1f(x);
        }
    }
    __shared__ float red[256];
    red[threadIdx.x] = s;
    __syncthreads();
    if (threadIdx.x < 64)
        g_partial[(b * 16 + ch) * 64 + threadIdx.x] =
            red[threadIdx.x] + red[64 + threadIdx.x] +
            red[128 + threadIdx.x] + red[192 + threadIdx.x];
}

__global__ void k_out(const float* __restrict__ Wout,
                      const float* __restrict__ bout,
                      float* __restrict__ out) {
    __shared__ float v[BB * 64];
    int t = threadIdx.x;
    {
        int b = t >> 6, h = t & 63;
        float s = 0.f;
#pragma unroll
        for (int p = 0; p < 16; p++) s += g_partial[(b * 16 + p) * 64 + h];
        v[t] = s;
    }
    __syncthreads();
    if (t < 128) {
        int b = t >> 5, o = t & 31;
        float s = 0.f;
#pragma unroll
        for (int hh = 0; hh < 64; hh++) s += v[b * 64 + hh] * Wout[hh * OO + o];
        out[b * OO + o] = s * (1.f / 8192.f) + bout[o];
    }
}

// ---------------- launcher ----------------
extern "C" void kernel_launch(void* const* d_in, const int* in_sizes, int n_in,
                              void* d_out, int out_size) {
    const float* nodes = (const float*)d_in[0];
    const float* edges = (const float*)d_in[1];
    const float* W_emb = (const float*)d_in[2];
    const float* b_emb = (const float*)d_in[3];
    const float* Wf0   = (const float*)d_in[4];
    const float* w1_0  = (const float*)d_in[5];
    const float* b1_0  = (const float*)d_in[6];
    const float* w2_0  = (const float*)d_in[7];
    const float* b2_0  = (const float*)d_in[8];
    const float* bias0 = (const float*)d_in[9];
    const float* Wf1   = (const float*)d_in[10];
    const float* w1_1  = (const float*)d_in[11];
    const float* b1_1  = (const float*)d_in[12];
    const float* w2_1  = (const float*)d_in[13];
    const float* b2_1  = (const float*)d_in[14];
    const float* bias1 = (const float*)d_in[15];
    const float* W_out = (const float*)d_in[16];
    const float* b_out = (const float*)d_in[17];
    float* out = (float*)d_out;

    k_split_edges<<<BNN / 2 / 256, 256>>>(edges);
    k_embed<<<(BB * NN) / 4, 256>>>(nodes, W_emb, b_emb);

    // ---- layer 0 (DIN = 64) ----
    k_wh<64><<<dim3(NN / 64, BB, EH), 128>>>(Wf0);
    k_a12<<<(CC * NN * 32) / 256, 256>>>(w1_0, b1_0, w2_0, b2_0);
    k_stats<<<dim3(4, 8, CC), 256>>>();
    k_sred<<<CC * NN / 256, 256>>>();
    k_whnT<<<dim3(NN / 64, CC), 256>>>();
    k_msg_mma<0><<<dim3(NN / 128, CC), 256>>>(bias0);

    // ---- layer 1 (DIN = 256) ----
    k_wh<256><<<dim3(NN / 64, BB, EH), 128>>>(Wf1);
    k_a12<<<(CC * NN * 32) / 256, 256>>>(w1_1, b1_1, w2_1, b2_1);
    k_stats<<<dim3(4, 8, CC), 256>>>();
    k_sred<<<CC * NN / 256, 256>>>();
    k_whnT<<<dim3(NN / 64, CC), 256>>>();
    k_msg_mma<1><<<dim3(NN / 128, CC), 256>>>(bias1);

    // ---- final reduction + output head ----
    k_reduce1<<<dim3(16, BB), 256>>>();
    k_out<<<1, 256>>>(W_out, b_out, out);
}